// round 17
// baseline (speedup 1.0000x reference)
#include <cuda_runtime.h>
#include <cuda_bf16.h>

#define B 8
#define C 256
#define HW 2304
#define DK 32
#define C2 512

#define M_TAB 2048
#define ALPHA 8.0f
#define PI_F 3.14159265358979323846f

#define NP1BLK 64     // p1 blocks: b(8) x ctile(8), 512 threads each
#define NTABBLK 128   // table blocks: 16 entries each (1 per warp)
#define NPREPBLK B    // prep blocks

// Scratch (device globals — zero-initialized; counters reset by consumer)
__device__ float g_tp[8 * B * C2]; // p1 partials: [ct][b][j]
__device__ float g_vg[B * C];      // vg = Wv @ GvT
__device__ float g_wqk[B * C];     // wqk = kg @ Wq
__device__ float g_qb[B];          // qb = bq . kg
__device__ float g_tab[M_TAB];     // s(a) table on a = ALPHA*tan(u) grid
__device__ unsigned int g_cnt1[B]; // per-batch p1-done counters

__device__ __forceinline__ float ex2f(float x) {
    float y;
    asm("ex2.approx.ftz.f32 %0, %1;" : "=f"(y) : "f"(x));
    return y;
}

__device__ __forceinline__ float warp_sum(float v) {
    #pragma unroll
    for (int o = 16; o; o >>= 1) v += __shfl_xor_sync(0xffffffffu, v, o);
    return v;
}

__device__ __forceinline__ unsigned int ld_acquire_gpu(unsigned int* p) {
    unsigned int v;
    asm volatile("ld.acquire.gpu.u32 %0, [%1];" : "=r"(v) : "l"(p) : "memory");
    return v;
}

// ---------------------------------------------------------------------------
// K1: grid 200 x 512.
// blocks 0..63   : p1 partials — b = blk>>3, ct = blk&7, j = tid.
// blocks 64..191 : s(a) table — 16 entries per block, one per warp.
// blocks 192..199: per-batch prep — spin on g_cnt1[b]==8, then combine.
// All 200 blocks are wave-1 resident; p1 has lowest indices. Deadlock-free.
// ---------------------------------------------------------------------------
__global__ __launch_bounds__(512)
void k1_kernel(const float* __restrict__ text,
               const float* __restrict__ Wg1,  const float* __restrict__ l,
               const float* __restrict__ bg1,
               const float* __restrict__ ln_g, const float* __restrict__ ln_b,
               const float* __restrict__ Wg2,  const float* __restrict__ bg2,
               const float* __restrict__ Wq,   const float* __restrict__ bq,
               const float* __restrict__ Wk,   const float* __restrict__ Wv)
{
    const int tid = threadIdx.x;
    const int lane = tid & 31, wid = tid >> 5;   // 16 warps
    const int blk = blockIdx.x;

    if (blk < NP1BLK) {
        // ---------------- p1 block ----------------
        const int b  = blk >> 3;
        const int ct = blk & 7;

        __shared__ float text_s[32];
        if (tid < 32) text_s[tid] = text[b * C + ct * 32 + tid];
        __syncthreads();

        float acc = 0.0f;
        #pragma unroll
        for (int cc = 0; cc < 32; cc++) {
            acc = fmaf(text_s[cc], Wg1[(ct * 32 + cc) * C2 + tid], acc);
        }
        g_tp[ct * (B * C2) + b * C2 + tid] = acc;

        __syncthreads();
        if (tid == 0) {
            __threadfence();
            atomicAdd(&g_cnt1[b], 1u);
        }
        return;
    }

    if (blk < NP1BLK + NTABBLK) {
        // ---------------- table block (16 warps, 1 entry each) --------------
        const int tblk = blk - NP1BLK;           // 0..127
        __shared__ float ls[HW];
        __shared__ float rmx[16], rmn[16];

        float mx = -1e30f, mn = 1e30f;
        #pragma unroll
        for (int j = tid; j < HW; j += 512) {
            const float v = l[j];
            ls[j] = v;
            mx = fmaxf(mx, v);
            mn = fminf(mn, v);
        }
        #pragma unroll
        for (int o = 16; o; o >>= 1) {
            mx = fmaxf(mx, __shfl_xor_sync(0xffffffffu, mx, o));
            mn = fminf(mn, __shfl_xor_sync(0xffffffffu, mn, o));
        }
        if (lane == 0) { rmx[wid] = mx; rmn[wid] = mn; }
        __syncthreads();
        float lmax = rmx[0], lmin = rmn[0];
        #pragma unroll
        for (int k = 1; k < 16; k++) {
            lmax = fmaxf(lmax, rmx[k]);
            lmin = fminf(lmin, rmn[k]);
        }

        // warp wid computes entry e = tblk*16 + wid
        const int e = tblk * 16 + wid;
        const float u = (e + 0.5f) * (PI_F / M_TAB) - 0.5f * PI_F;
        const float al = ALPHA * tanf(u) * 1.4426950408889634f;
        const float m2 = (al > 0.0f) ? al * lmax : al * lmin;
        float S = 0.0f, T = 0.0f;
        #pragma unroll 8
        for (int j = lane; j < HW; j += 32) {
            const float lj = ls[j];
            const float ev = ex2f(fmaf(al, lj, -m2));
            S += ev;
            T = fmaf(lj, ev, T);
        }
        S = warp_sum(S);
        T = warp_sum(T);
        if (lane == 0) g_tab[e] = T / S;
        return;
    }

    // ---------------- prep block (one batch, 512 threads) ----------------
    const int b = blk - (NP1BLK + NTABBLK);

    __shared__ float t_s[C2];
    __shared__ float gv_s[C];
    __shared__ float part_f[2048];               // 8 k-chunks x 256 c
    __shared__ float kg_s[DK];
    __shared__ float red[16];
    __shared__ float bcast[2];

    // wait for this batch's 8 p1 blocks, then reset counter for next launch
    if (tid == 0) {
        while (ld_acquire_gpu(&g_cnt1[b]) < 8u) __nanosleep(32);
        g_cnt1[b] = 0;                           // replay-safe reset
    }
    __syncthreads();
    __threadfence();

    // ---- combine p1 partials (fixed order: deterministic) ----
    float v = bg1[tid];
    #pragma unroll
    for (int ct = 0; ct < 8; ct++) v += g_tp[ct * (B * C2) + b * C2 + tid];

    // ---- LayerNorm + exact GELU ----
    float s1 = warp_sum(v);
    if (lane == 0) red[wid] = s1;
    __syncthreads();
    if (wid == 0) {
        float r = (lane < 16) ? red[lane] : 0.0f;
        r = warp_sum(r);
        if (lane == 0) bcast[0] = r * (1.0f / C2);
    }
    __syncthreads();
    const float mu = bcast[0];
    const float d = v - mu;
    float s2 = warp_sum(d * d);
    if (lane == 0) red[wid] = s2;
    __syncthreads();
    if (wid == 0) {
        float r = (lane < 16) ? red[lane] : 0.0f;
        r = warp_sum(r);
        if (lane == 0) bcast[1] = rsqrtf(r * (1.0f / C2) + 1e-5f);
    }
    __syncthreads();
    {
        float x = d * bcast[1] * ln_g[tid] + ln_b[tid];
        t_s[tid] = 0.5f * x * (1.0f + erff(x * 0.7071067811865476f));
    }
    __syncthreads();

    // ---- GvT[c] = sum_k t[k] * Wg2[k*C + c] + bg2[c] : 2-acc ILP ----
    {
        const int q = tid & 63;       // c-group: c = 4q .. 4q+3
        const int h = tid >> 6;       // k-chunk: k in [h*64, h*64+64)
        const float4* W4 = (const float4*)Wg2;   // [512][64] float4
        float4 a0 = make_float4(0.f, 0.f, 0.f, 0.f);
        float4 a1 = a0;
        const int k0 = h * 64;
        #pragma unroll 16
        for (int kk = 0; kk < 32; kk++) {
            const float t0 = t_s[k0 + kk];
            const float t1 = t_s[k0 + 32 + kk];
            const float4 w0 = W4[(k0 + kk) * 64 + q];
            const float4 w1 = W4[(k0 + 32 + kk) * 64 + q];
            a0.x = fmaf(t0, w0.x, a0.x); a0.y = fmaf(t0, w0.y, a0.y);
            a0.z = fmaf(t0, w0.z, a0.z); a0.w = fmaf(t0, w0.w, a0.w);
            a1.x = fmaf(t1, w1.x, a1.x); a1.y = fmaf(t1, w1.y, a1.y);
            a1.z = fmaf(t1, w1.z, a1.z); a1.w = fmaf(t1, w1.w, a1.w);
        }
        part_f[h * 256 + 4 * q + 0] = a0.x + a1.x;
        part_f[h * 256 + 4 * q + 1] = a0.y + a1.y;
        part_f[h * 256 + 4 * q + 2] = a0.z + a1.z;
        part_f[h * 256 + 4 * q + 3] = a0.w + a1.w;
    }
    __syncthreads();
    if (tid < C) {
        float g = bg2[tid];
        #pragma unroll
        for (int h = 0; h < 8; h++) g += part_f[h * 256 + tid];
        gv_s[tid] = g;
    }
    __syncthreads();

    // ---- vg[c] = Wv[c,:] . gv : 16 outputs/warp, pipelined reductions ----
    {
        const float4* Wv4 = (const float4*)Wv;        // [256][64] float4
        const float4* gv4 = (const float4*)gv_s;
        const float4 gA = gv4[lane];
        const float4 gB = gv4[32 + lane];
        #pragma unroll
        for (int g = 0; g < 2; g++) {
            float part[8];
            #pragma unroll
            for (int oo = 0; oo < 8; oo++) {
                const int c = wid * 16 + g * 8 + oo;
                const float4 wA = Wv4[c * 64 + lane];
                const float4 wB = Wv4[c * 64 + 32 + lane];
                part[oo] = wA.x * gA.x + wA.y * gA.y + wA.z * gA.z + wA.w * gA.w
                         + wB.x * gB.x + wB.y * gB.y + wB.z * gB.z + wB.w * gB.w;
            }
            #pragma unroll
            for (int oo = 0; oo < 8; oo++) part[oo] = warp_sum(part[oo]);
            if (lane == 0) {
                #pragma unroll
                for (int oo = 0; oo < 8; oo++)
                    g_vg[b * C + wid * 16 + g * 8 + oo] = part[oo];
            }
        }
        // ---- kg[d] = Wk[d,:] . gv : 2 outputs/warp ----
        const float4* Wk4 = (const float4*)Wk;        // [32][64] float4
        {
            float pk[2];
            #pragma unroll
            for (int oo = 0; oo < 2; oo++) {
                const int dd = wid * 2 + oo;
                const float4 wA = Wk4[dd * 64 + lane];
                const float4 wB = Wk4[dd * 64 + 32 + lane];
                pk[oo] = wA.x * gA.x + wA.y * gA.y + wA.z * gA.z + wA.w * gA.w
                       + wB.x * gB.x + wB.y * gB.y + wB.z * gB.z + wB.w * gB.w;
            }
            #pragma unroll
            for (int oo = 0; oo < 2; oo++) pk[oo] = warp_sum(pk[oo]);
            if (lane == 0) {
                kg_s[wid * 2 + 0] = pk[0];
                kg_s[wid * 2 + 1] = pk[1];
            }
        }
    }
    __syncthreads();

    // ---- wqk[c] = sum_d kg[d] * Wq[d*C + c];  qb = bq . kg ----
    if (tid < C) {
        float acc = 0.0f;
        #pragma unroll
        for (int dd = 0; dd < DK; dd++) acc = fmaf(kg_s[dd], Wq[dd * C + tid], acc);
        g_wqk[b * C + tid] = acc;
    }
    if (wid == 0) {
        float p = bq[lane] * kg_s[lane];
        p = warp_sum(p);
        if (lane == 0) g_qb[b] = p;
    }
}

// ---------------------------------------------------------------------------
// Attention: pure memory stream. block = 256 thr; warp s owns channels
// [32s, 32s+32) for the block's 32 pixels (lane = pixel). img read ONCE into
// registers; s(a) via 4-tap Catmull-Rom from the smem-cached table.
// grid (72, 8), occ 4.
// ---------------------------------------------------------------------------
__global__ __launch_bounds__(256, 4)
void attn_kernel(const float* __restrict__ img,
                 const float* __restrict__ bv,
                 const float* __restrict__ gamma_p,
                 float* __restrict__ out)
{
    const int b = blockIdx.y;
    const int tid = threadIdx.x;
    const int p = tid & 31;      // pixel within block (lane)
    const int s = tid >> 5;      // channel-split 0..7 (warp)
    const int i = blockIdx.x * 32 + p;
    const int c0 = s * 32;

    __shared__ float tab_s[M_TAB];
    __shared__ float wq[C];
    __shared__ float vgs[C];
    __shared__ float bvs[C];
    __shared__ float partA[256];

    // front-batch img loads (32 contiguous channels per thread) into registers
    float im[32];
    const float* xb = img + (size_t)b * C * HW + (size_t)c0 * HW + i;
    #pragma unroll
    for (int cc = 0; cc < 32; cc++) im[cc] = xb[(size_t)cc * HW];

    const float gm = *gamma_p;
    const float qb = g_qb[b];

    // smem fills overlap the in-flight img loads
    #pragma unroll
    for (int k = tid; k < M_TAB; k += 256) tab_s[k] = g_tab[k];
    wq[tid]  = g_wqk[b * C + tid];
    vgs[tid] = g_vg[b * C + tid];
    bvs[tid] = bv[tid];
    __syncthreads();

    // partial dot over this thread's 32 channels
    float a = 0.0f;
    #pragma unroll
    for (int cc = 0; cc < 32; cc++) a = fmaf(wq[c0 + cc], im[cc], a);
    partA[tid] = a;
    __syncthreads();
    float af = qb;
    #pragma unroll
    for (int k = 0; k < 8; k++) af += partA[k * 32 + p];

    // s(af) via table: u = atan(af/ALPHA); cubic Catmull-Rom in u-grid
    const float u = atanf(af * (1.0f / ALPHA));
    const float idx = u * (M_TAB / PI_F) + (M_TAB * 0.5f - 0.5f);
    const float fi = floorf(idx);
    const float t = idx - fi;
    const int i1 = (int)fi;
    const int j0 = max(i1 - 1, 0);
    const int j1 = min(max(i1, 0), M_TAB - 1);
    const int j2 = min(i1 + 1, M_TAB - 1);
    const int j3 = min(i1 + 2, M_TAB - 1);
    const float p0 = tab_s[j0], p1v = tab_s[j1], p2 = tab_s[j2], p3 = tab_s[j3];
    const float sv = p1v + 0.5f * t * (p2 - p0
                   + t * (2.0f * p0 - 5.0f * p1v + 4.0f * p2 - p3
                   + t * (3.0f * (p1v - p2) + p3 - p0)));

    // out[b,c,i] = img + gamma * (vg[c]*sv + bv[c]) using register-cached img
    float* ob = out + (size_t)b * C * HW + (size_t)c0 * HW + i;
    #pragma unroll
    for (int cc = 0; cc < 32; cc++) {
        ob[(size_t)cc * HW] = fmaf(gm, fmaf(vgs[c0 + cc], sv, bvs[c0 + cc]), im[cc]);
    }
}

extern "C" void kernel_launch(void* const* d_in, const int* in_sizes, int n_in,
                              void* d_out, int out_size)
{
    const float* img   = (const float*)d_in[0];
    const float* text  = (const float*)d_in[1];
    const float* l     = (const float*)d_in[2];
    const float* Wg1   = (const float*)d_in[3];
    const float* bg1   = (const float*)d_in[4];
    const float* ln_g  = (const float*)d_in[5];
    const float* ln_b  = (const float*)d_in[6];
    const float* Wg2   = (const float*)d_in[7];
    const float* bg2   = (const float*)d_in[8];
    const float* Wq    = (const float*)d_in[9];
    const float* bq    = (const float*)d_in[10];
    const float* Wk    = (const float*)d_in[11];
    // d_in[12] = bk : cancels in softmax, unused
    const float* Wv    = (const float*)d_in[13];
    const float* bv    = (const float*)d_in[14];
    const float* gamma = (const float*)d_in[15];
    float* out = (float*)d_out;

    k1_kernel<<<NP1BLK + NTABBLK + NPREPBLK, 512>>>(
        text, Wg1, l, bg1, ln_g, ln_b, Wg2, bg2, Wq, bq, Wk, Wv);
    dim3 grid(HW / 32, B);
    attn_kernel<<<grid, 256>>>(img, bv, gamma, out);
}